// round 1
// baseline (speedup 1.0000x reference)
#include <cuda_runtime.h>
#include <cuda_bf16.h>

#define N_NODES 100000
#define N_EDGES 300000
#define N_GRAPHS 2048
#define IN_DIM 38
#define HID 256
#define LAYERS 5
#define BN_EPS 1e-5f

// ---------------- device scratch (no allocations allowed) ----------------
__device__ float g_h[N_NODES * HID];     // node features (post-activation)
__device__ float g_z[N_NODES * HID];     // (1+eps)h + agg  /  z2 (MLP out)
__device__ float g_t[N_NODES * HID];     // MLP hidden
__device__ float g_colsum[HID];
__device__ float g_colsq[HID];
__device__ float g_scale[HID];
__device__ float g_shift[HID];
__device__ float g_pool[N_GRAPHS * HID];
__device__ float g_cnt[N_GRAPHS];
__device__ float g_r1[N_GRAPHS * HID];

// ---------------- projection: h = x @ Wp + bp ----------------
// Block handles 32 rows; Wp (38x256) staged in smem; each thread owns one column.
__global__ void __launch_bounds__(256) proj_kernel(const float* __restrict__ x,
                                                   const float* __restrict__ Wp,
                                                   const float* __restrict__ bp) {
    __shared__ float xs[32][IN_DIM];
    __shared__ float ws[IN_DIM * HID];
    const int tid = threadIdx.x;
    for (int i = tid; i < IN_DIM * HID; i += 256) ws[i] = Wp[i];
    const int row0 = blockIdx.x * 32;
    for (int i = tid; i < 32 * IN_DIM; i += 256) {
        int r = i / IN_DIM, k = i % IN_DIM;
        xs[r][k] = (row0 + r < N_NODES) ? x[(row0 + r) * IN_DIM + k] : 0.f;
    }
    __syncthreads();
    float acc[32];
#pragma unroll
    for (int r = 0; r < 32; r++) acc[r] = 0.f;
    const int col = tid;
#pragma unroll
    for (int k = 0; k < IN_DIM; k++) {
        float w = ws[k * HID + col];
#pragma unroll
        for (int r = 0; r < 32; r++) acc[r] = fmaf(xs[r][k], w, acc[r]);
    }
    const float b = bp[col];
    for (int r = 0; r < 32; r++) {
        int rr = row0 + r;
        if (rr < N_NODES) g_h[rr * HID + col] = acc[r] + b;
    }
}

// ---------------- z = (1+eps[l]) * h ----------------
__global__ void scale_init_kernel(const float* __restrict__ eps, int l) {
    const float s = 1.f + eps[l];
    const int n4 = N_NODES * HID / 4;
    const float4* h4 = reinterpret_cast<const float4*>(g_h);
    float4* z4 = reinterpret_cast<float4*>(g_z);
    for (int i = blockIdx.x * blockDim.x + threadIdx.x; i < n4;
         i += gridDim.x * blockDim.x) {
        float4 v = h4[i];
        v.x *= s; v.y *= s; v.z *= s; v.w *= s;
        z4[i] = v;
    }
}

// ---------------- scatter: z[dst] += h[src] (64 threads per edge) ----------------
__global__ void scatter_kernel(const int* __restrict__ src, const int* __restrict__ dst) {
    const int idx = blockIdx.x * blockDim.x + threadIdx.x;
    const int e = idx >> 6;
    if (e >= N_EDGES) return;
    const int lane = idx & 63;
    const int s = src[e];
    const int d = dst[e];
    float4 v = *reinterpret_cast<const float4*>(g_h + s * HID + lane * 4);
    float* zp = g_z + d * HID + lane * 4;
    atomicAdd(zp + 0, v.x);
    atomicAdd(zp + 1, v.y);
    atomicAdd(zp + 2, v.z);
    atomicAdd(zp + 3, v.w);
}

// ---------------- SGEMM: C[M,N] = A[M,K] @ B[K,N] + bias, optional relu ----------------
// BM=128, BN=128, BK=8, 256 threads, 8x8 register tiles.
template <bool RELU>
__global__ void __launch_bounds__(256) sgemm_kernel(const float* __restrict__ A,
                                                    const float* __restrict__ B,
                                                    const float* __restrict__ bias,
                                                    float* __restrict__ C,
                                                    int M, int N, int K) {
    __shared__ float As[8][128];
    __shared__ float Bs[8][128];
    const int tid = threadIdx.x;
    const int row0 = blockIdx.x * 128;
    const int col0 = blockIdx.y * 128;
    const int tr = (tid >> 4) << 3;
    const int tc = (tid & 15) << 3;
    const int arow = tid >> 1;
    const int ak4 = (tid & 1) * 4;
    const int brow = tid >> 5;
    const int bcol = (tid & 31) * 4;

    float acc[8][8];
#pragma unroll
    for (int i = 0; i < 8; i++)
#pragma unroll
        for (int j = 0; j < 8; j++) acc[i][j] = 0.f;

    const int gar = row0 + arow;
    const bool arow_ok = (gar < M);

    for (int k0 = 0; k0 < K; k0 += 8) {
        float4 av = make_float4(0.f, 0.f, 0.f, 0.f);
        if (arow_ok)
            av = *reinterpret_cast<const float4*>(A + (size_t)gar * K + k0 + ak4);
        As[ak4 + 0][arow] = av.x;
        As[ak4 + 1][arow] = av.y;
        As[ak4 + 2][arow] = av.z;
        As[ak4 + 3][arow] = av.w;
        float4 bv = *reinterpret_cast<const float4*>(B + (size_t)(k0 + brow) * N + col0 + bcol);
        *reinterpret_cast<float4*>(&Bs[brow][bcol]) = bv;
        __syncthreads();
#pragma unroll
        for (int k = 0; k < 8; k++) {
            float ra[8], rb[8];
#pragma unroll
            for (int i = 0; i < 8; i++) ra[i] = As[k][tr + i];
#pragma unroll
            for (int j = 0; j < 8; j++) rb[j] = Bs[k][tc + j];
#pragma unroll
            for (int i = 0; i < 8; i++)
#pragma unroll
                for (int j = 0; j < 8; j++) acc[i][j] = fmaf(ra[i], rb[j], acc[i][j]);
        }
        __syncthreads();
    }

#pragma unroll
    for (int i = 0; i < 8; i++) {
        int r = row0 + tr + i;
        if (r >= M) break;
#pragma unroll
        for (int j = 0; j < 8; j += 4) {
            float4 v;
            v.x = acc[i][j + 0] + bias[col0 + tc + j + 0];
            v.y = acc[i][j + 1] + bias[col0 + tc + j + 1];
            v.z = acc[i][j + 2] + bias[col0 + tc + j + 2];
            v.w = acc[i][j + 3] + bias[col0 + tc + j + 3];
            if (RELU) {
                v.x = fmaxf(v.x, 0.f); v.y = fmaxf(v.y, 0.f);
                v.z = fmaxf(v.z, 0.f); v.w = fmaxf(v.w, 0.f);
            }
            *reinterpret_cast<float4*>(C + (size_t)r * N + col0 + tc + j) = v;
        }
    }
}

// ---------------- BN ----------------
__global__ void zero_stats_kernel() {
    g_colsum[threadIdx.x] = 0.f;
    g_colsq[threadIdx.x] = 0.f;
}

__global__ void bn_stats_kernel() {
    const int col = threadIdx.x;
    const int rows = (N_NODES + gridDim.x - 1) / gridDim.x;
    const int r0 = blockIdx.x * rows;
    const int r1 = min(r0 + rows, N_NODES);
    float s = 0.f, q = 0.f;
    for (int r = r0; r < r1; r++) {
        float v = g_z[r * HID + col];
        s += v;
        q = fmaf(v, v, q);
    }
    atomicAdd(&g_colsum[col], s);
    atomicAdd(&g_colsq[col], q);
}

__global__ void bn_finalize_kernel(const float* __restrict__ gammas,
                                   const float* __restrict__ betas, int l) {
    const int c = threadIdx.x;
    const float inv = 1.f / (float)N_NODES;
    float mu = g_colsum[c] * inv;
    float var = g_colsq[c] * inv - mu * mu;
    float rs = rsqrtf(var + BN_EPS);
    float sc = gammas[l * HID + c] * rs;
    g_scale[c] = sc;
    g_shift[c] = betas[l * HID + c] - mu * sc;
}

// h = relu(z * scale + shift)
__global__ void bn_apply_kernel() {
    const int n4 = N_NODES * HID / 4;
    const float4* z4 = reinterpret_cast<const float4*>(g_z);
    float4* h4 = reinterpret_cast<float4*>(g_h);
    for (int i = blockIdx.x * blockDim.x + threadIdx.x; i < n4;
         i += gridDim.x * blockDim.x) {
        int col = (i * 4) & (HID - 1);
        float4 v = z4[i];
        float4 sc = *reinterpret_cast<const float4*>(g_scale + col);
        float4 sh = *reinterpret_cast<const float4*>(g_shift + col);
        v.x = fmaxf(fmaf(v.x, sc.x, sh.x), 0.f);
        v.y = fmaxf(fmaf(v.y, sc.y, sh.y), 0.f);
        v.z = fmaxf(fmaf(v.z, sc.z, sh.z), 0.f);
        v.w = fmaxf(fmaf(v.w, sc.w, sh.w), 0.f);
        h4[i] = v;
    }
}

// ---------------- pooling ----------------
__global__ void zero_pool_kernel() {
    int i = blockIdx.x * 256 + threadIdx.x;
    g_pool[i] = 0.f;
    if (i < N_GRAPHS) g_cnt[i] = 0.f;
}

__global__ void pool_add_kernel(const int* __restrict__ batch) {
    const int idx = blockIdx.x * blockDim.x + threadIdx.x;
    if (idx >= N_NODES * 64) return;
    const int node = idx >> 6;
    const int lane = idx & 63;
    const int g = batch[node];
    float4 v = *reinterpret_cast<const float4*>(g_h + node * HID + lane * 4);
    float* p = g_pool + g * HID + lane * 4;
    atomicAdd(p + 0, v.x);
    atomicAdd(p + 1, v.y);
    atomicAdd(p + 2, v.z);
    atomicAdd(p + 3, v.w);
}

__global__ void cnt_kernel(const int* __restrict__ batch) {
    const int n = blockIdx.x * blockDim.x + threadIdx.x;
    if (n < N_NODES) atomicAdd(&g_cnt[batch[n]], 1.f);
}

__global__ void pool_div_kernel() {
    const int b = blockIdx.x;
    const int t = threadIdx.x;
    g_pool[b * HID + t] /= fmaxf(g_cnt[b], 1.f);
}

// ---------------- final readout: out[g] = r1[g,:] . Wr2 + br2 ----------------
__global__ void readout2_kernel(const float* __restrict__ Wr2,
                                const float* __restrict__ br2,
                                float* __restrict__ out) {
    __shared__ float red[256];
    const int g = blockIdx.x;
    const int t = threadIdx.x;
    red[t] = g_r1[g * HID + t] * Wr2[t];
    __syncthreads();
    for (int s = 128; s > 0; s >>= 1) {
        if (t < s) red[t] += red[t + s];
        __syncthreads();
    }
    if (t == 0) out[g] = red[0] + br2[0];
}

// ---------------- host launcher ----------------
extern "C" void kernel_launch(void* const* d_in, const int* in_sizes, int n_in,
                              void* d_out, int out_size) {
    const float* x      = (const float*)d_in[0];
    const int*   ei     = (const int*)d_in[1];
    const int*   batch  = (const int*)d_in[2];
    const float* Wp     = (const float*)d_in[3];
    const float* bp     = (const float*)d_in[4];
    const float* eps    = (const float*)d_in[5];
    const float* W1s    = (const float*)d_in[6];
    const float* b1s    = (const float*)d_in[7];
    const float* W2s    = (const float*)d_in[8];
    const float* b2s    = (const float*)d_in[9];
    const float* gammas = (const float*)d_in[10];
    const float* betas  = (const float*)d_in[11];
    const float* Wr1    = (const float*)d_in[12];
    const float* br1    = (const float*)d_in[13];
    const float* Wr2    = (const float*)d_in[14];
    const float* br2    = (const float*)d_in[15];
    float* out = (float*)d_out;

    const int* src = ei;
    const int* dst = ei + N_EDGES;

    // device-global scratch addresses (host-visible pointers for generic SGEMM)
    void *p_h, *p_z, *p_t, *p_pool, *p_r1;
    cudaGetSymbolAddress(&p_h, g_h);
    cudaGetSymbolAddress(&p_z, g_z);
    cudaGetSymbolAddress(&p_t, g_t);
    cudaGetSymbolAddress(&p_pool, g_pool);
    cudaGetSymbolAddress(&p_r1, g_r1);
    float* dh = (float*)p_h;
    float* dz = (float*)p_z;
    float* dt = (float*)p_t;
    float* dpool = (float*)p_pool;
    float* dr1 = (float*)p_r1;

    // 1) projection
    proj_kernel<<<(N_NODES + 31) / 32, 256>>>(x, Wp, bp);

    const dim3 ggrid((N_NODES + 127) / 128, HID / 128);

    // 2) GIN layers
    for (int l = 0; l < LAYERS; l++) {
        scale_init_kernel<<<4096, 256>>>(eps, l);
        scatter_kernel<<<(N_EDGES * 64 + 255) / 256, 256>>>(src, dst);
        sgemm_kernel<true><<<ggrid, 256>>>(dz, W1s + l * HID * HID, b1s + l * HID,
                                           dt, N_NODES, HID, HID);
        sgemm_kernel<false><<<ggrid, 256>>>(dt, W2s + l * HID * HID, b2s + l * HID,
                                            dz, N_NODES, HID, HID);
        zero_stats_kernel<<<1, 256>>>();
        bn_stats_kernel<<<512, 256>>>();
        bn_finalize_kernel<<<1, 256>>>(gammas, betas, l);
        bn_apply_kernel<<<4096, 256>>>();
    }

    // 3) global mean pool
    zero_pool_kernel<<<N_GRAPHS, 256>>>();
    pool_add_kernel<<<(N_NODES * 64 + 255) / 256, 256>>>(batch);
    cnt_kernel<<<(N_NODES + 255) / 256, 256>>>(batch);
    pool_div_kernel<<<N_GRAPHS, 256>>>();

    // 4) readout MLP
    const dim3 rgrid(N_GRAPHS / 128, HID / 128);
    sgemm_kernel<true><<<rgrid, 256>>>(dpool, Wr1, br1, dr1, N_GRAPHS, HID, HID);
    readout2_kernel<<<N_GRAPHS, 256>>>(Wr2, br2, out);
}

// round 3
// speedup vs baseline: 1.2383x; 1.2383x over previous
#include <cuda_runtime.h>
#include <cuda_bf16.h>
#include <cstdint>

#define N_NODES 100000
#define N_EDGES 300000
#define N_GRAPHS 2048
#define IN_DIM 38
#define HID 256
#define LAYERS 5
#define BN_EPS 1e-5f

// ---------------- device scratch ----------------
__device__ float g_h[N_NODES * HID];
__device__ float g_z[N_NODES * HID];
__device__ float g_t[N_NODES * HID];
__device__ float g_colsum[HID];
__device__ float g_colsq[HID];
__device__ float g_scale[HID];
__device__ float g_shift[HID];
__device__ float g_pool[N_GRAPHS * HID];
__device__ float g_r1[N_GRAPHS * HID];
__device__ int g_deg[N_NODES];
__device__ int g_fill[N_NODES];
__device__ int g_off[N_NODES + 1];
__device__ int g_csr[N_EDGES];

// ================= bf16 split-GEMM via mma.sync (baseline PTX, sm_80+) =================
// C[M,256] = A[M,256] @ W[256,256] + bias (optional relu)
// A,W split into bf16 hi + lo residual; 3 passes: ah*bh + ah*bl + al*bh.
#define MMA_BF16(c, a0, a1, a2, a3, b0, b1)                                    \
    asm volatile(                                                              \
        "mma.sync.aligned.m16n8k16.row.col.f32.bf16.bf16.f32 "                 \
        "{%0,%1,%2,%3}, {%4,%5,%6,%7}, {%8,%9}, {%0,%1,%2,%3};"                \
        : "+f"((c)[0]), "+f"((c)[1]), "+f"((c)[2]), "+f"((c)[3])               \
        : "r"(a0), "r"(a1), "r"(a2), "r"(a3), "r"(b0), "r"(b1))

// smem: 2 stages; per stage: Ahi/Alo 128 rows x 40 bf16 (80B) = 10240B each,
//                            Bhi/Blo 128 cols x 40 bf16        = 10240B each
#define AH_OFF(b) ((b) * 40960)
#define AL_OFF(b) ((b) * 40960 + 10240)
#define BH_OFF(b) ((b) * 40960 + 20480)
#define BL_OFF(b) ((b) * 40960 + 30720)
#define GEMM_SMEM (2 * 40960)

__device__ __forceinline__ void split_bf16(float v, uint16_t& hi, uint16_t& lo) {
    __nv_bfloat16 bh = __float2bfloat16(v);
    float resid = v - __bfloat162float(bh);
    __nv_bfloat16 bl = __float2bfloat16(resid);
    hi = *reinterpret_cast<uint16_t*>(&bh);
    lo = *reinterpret_cast<uint16_t*>(&bl);
}

template <bool RELU>
__global__ void __launch_bounds__(256, 1)
gemm_bf16_kernel(const float* __restrict__ A, const float* __restrict__ W,
                 const float* __restrict__ bias, float* __restrict__ C, int M) {
    extern __shared__ char sm[];
    const int tid = threadIdx.x;
    const int lane = tid & 31;
    const int wid = tid >> 5;
    const int wm = wid & 3;     // warp row (4)
    const int wn = wid >> 2;    // warp col (2)
    const int gq = lane >> 2;   // group id 0..7
    const int tq = lane & 3;    // thread-in-group 0..3
    const int row0 = blockIdx.x * 128;
    const int col0 = blockIdx.y * 128;

    // global-load mapping
    const int ar = tid >> 3;          // A row (0..31), +32*i
    const int akq = tid & 7;          // A float4 index within 32-float row
    const int bk = tid >> 5;          // W k-row (0..7), +8*i
    const int bn4 = (tid & 31) * 4;   // W col offset

    float4 asg[4], bsg[4];

    float acc[2][8][4];
#pragma unroll
    for (int i = 0; i < 2; i++)
#pragma unroll
        for (int n = 0; n < 8; n++)
#pragma unroll
            for (int q = 0; q < 4; q++) acc[i][n][q] = 0.f;

    auto ldg_chunk = [&](int k0) {
#pragma unroll
        for (int i = 0; i < 4; i++) {
            int gr = row0 + ar + 32 * i;
            asg[i] = (gr < M)
                ? *reinterpret_cast<const float4*>(A + (size_t)gr * HID + k0 + akq * 4)
                : make_float4(0.f, 0.f, 0.f, 0.f);
            bsg[i] = *reinterpret_cast<const float4*>(
                W + (size_t)(k0 + bk + 8 * i) * HID + col0 + bn4);
        }
    };

    auto sts_chunk = [&](int b) {
#pragma unroll
        for (int i = 0; i < 4; i++) {
            // ---- A ----
            int r = ar + 32 * i;
            float av[4] = {asg[i].x, asg[i].y, asg[i].z, asg[i].w};
            uint16_t h[4], l[4];
#pragma unroll
            for (int d = 0; d < 4; d++) split_bf16(av[d], h[d], l[d]);
            uint2 hp = make_uint2((uint32_t)h[0] | ((uint32_t)h[1] << 16),
                                  (uint32_t)h[2] | ((uint32_t)h[3] << 16));
            uint2 lp = make_uint2((uint32_t)l[0] | ((uint32_t)l[1] << 16),
                                  (uint32_t)l[2] | ((uint32_t)l[3] << 16));
            *reinterpret_cast<uint2*>(sm + AH_OFF(b) + r * 80 + akq * 8) = hp;
            *reinterpret_cast<uint2*>(sm + AL_OFF(b) + r * 80 + akq * 8) = lp;
            // ---- B (transpose to [n][k]) ----
            int k = bk + 8 * i;
            float bv[4] = {bsg[i].x, bsg[i].y, bsg[i].z, bsg[i].w};
#pragma unroll
            for (int d = 0; d < 4; d++) {
                uint16_t bh, bl;
                split_bf16(bv[d], bh, bl);
                *reinterpret_cast<uint16_t*>(sm + BH_OFF(b) + (bn4 + d) * 80 + k * 2) = bh;
                *reinterpret_cast<uint16_t*>(sm + BL_OFF(b) + (bn4 + d) * 80 + k * 2) = bl;
            }
        }
    };

    auto compute = [&](int b) {
#pragma unroll
        for (int j = 0; j < 2; j++) {   // two k16 steps per BK=32 chunk
            const int kb = j * 32 + tq * 4;
            uint32_t ah[2][4], al[2][4];
#pragma unroll
            for (int i = 0; i < 2; i++) {
                int rb = wm * 32 + i * 16;
                const char* ph = sm + AH_OFF(b);
                const char* pl = sm + AL_OFF(b);
                ah[i][0] = *reinterpret_cast<const uint32_t*>(ph + (rb + gq) * 80 + kb);
                ah[i][1] = *reinterpret_cast<const uint32_t*>(ph + (rb + 8 + gq) * 80 + kb);
                ah[i][2] = *reinterpret_cast<const uint32_t*>(ph + (rb + gq) * 80 + kb + 16);
                ah[i][3] = *reinterpret_cast<const uint32_t*>(ph + (rb + 8 + gq) * 80 + kb + 16);
                al[i][0] = *reinterpret_cast<const uint32_t*>(pl + (rb + gq) * 80 + kb);
                al[i][1] = *reinterpret_cast<const uint32_t*>(pl + (rb + 8 + gq) * 80 + kb);
                al[i][2] = *reinterpret_cast<const uint32_t*>(pl + (rb + gq) * 80 + kb + 16);
                al[i][3] = *reinterpret_cast<const uint32_t*>(pl + (rb + 8 + gq) * 80 + kb + 16);
            }
#pragma unroll
            for (int n = 0; n < 8; n++) {
                int cb = wn * 64 + n * 8 + gq;
                uint32_t bh0 = *reinterpret_cast<const uint32_t*>(sm + BH_OFF(b) + cb * 80 + kb);
                uint32_t bh1 = *reinterpret_cast<const uint32_t*>(sm + BH_OFF(b) + cb * 80 + kb + 16);
                uint32_t bl0 = *reinterpret_cast<const uint32_t*>(sm + BL_OFF(b) + cb * 80 + kb);
                uint32_t bl1 = *reinterpret_cast<const uint32_t*>(sm + BL_OFF(b) + cb * 80 + kb + 16);
#pragma unroll
                for (int i = 0; i < 2; i++) {
                    MMA_BF16(acc[i][n], ah[i][0], ah[i][1], ah[i][2], ah[i][3], bh0, bh1);
                    MMA_BF16(acc[i][n], ah[i][0], ah[i][1], ah[i][2], ah[i][3], bl0, bl1);
                    MMA_BF16(acc[i][n], al[i][0], al[i][1], al[i][2], al[i][3], bh0, bh1);
                }
            }
        }
    };

    ldg_chunk(0);
    sts_chunk(0);
    __syncthreads();
#pragma unroll 1
    for (int c = 0; c < 8; c++) {
        int b = c & 1;
        if (c < 7) ldg_chunk((c + 1) * 32);
        compute(b);
        __syncthreads();
        if (c < 7) {
            sts_chunk(b ^ 1);
            __syncthreads();
        }
    }

    // epilogue
#pragma unroll
    for (int i = 0; i < 2; i++) {
        int r0 = row0 + wm * 32 + i * 16 + gq;
#pragma unroll
        for (int n = 0; n < 8; n++) {
            int col = col0 + wn * 64 + n * 8 + tq * 2;
            float b0 = bias[col], b1 = bias[col + 1];
            if (r0 < M) {
                float2 v;
                v.x = acc[i][n][0] + b0;
                v.y = acc[i][n][1] + b1;
                if (RELU) { v.x = fmaxf(v.x, 0.f); v.y = fmaxf(v.y, 0.f); }
                *reinterpret_cast<float2*>(C + (size_t)r0 * HID + col) = v;
            }
            if (r0 + 8 < M) {
                float2 v;
                v.x = acc[i][n][2] + b0;
                v.y = acc[i][n][3] + b1;
                if (RELU) { v.x = fmaxf(v.x, 0.f); v.y = fmaxf(v.y, 0.f); }
                *reinterpret_cast<float2*>(C + (size_t)(r0 + 8) * HID + col) = v;
            }
        }
    }
}

// ---------------- projection: h = x @ Wp + bp ----------------
__global__ void __launch_bounds__(256) proj_kernel(const float* __restrict__ x,
                                                   const float* __restrict__ Wp,
                                                   const float* __restrict__ bp) {
    __shared__ float xs[32][IN_DIM];
    __shared__ float ws[IN_DIM * HID];
    const int tid = threadIdx.x;
    for (int i = tid; i < IN_DIM * HID; i += 256) ws[i] = Wp[i];
    const int row0 = blockIdx.x * 32;
    for (int i = tid; i < 32 * IN_DIM; i += 256) {
        int r = i / IN_DIM, k = i % IN_DIM;
        xs[r][k] = (row0 + r < N_NODES) ? x[(row0 + r) * IN_DIM + k] : 0.f;
    }
    __syncthreads();
    float acc[32];
#pragma unroll
    for (int r = 0; r < 32; r++) acc[r] = 0.f;
    const int col = tid;
#pragma unroll
    for (int k = 0; k < IN_DIM; k++) {
        float w = ws[k * HID + col];
#pragma unroll
        for (int r = 0; r < 32; r++) acc[r] = fmaf(xs[r][k], w, acc[r]);
    }
    const float b = bp[col];
    for (int r = 0; r < 32; r++) {
        int rr = row0 + r;
        if (rr < N_NODES) g_h[rr * HID + col] = acc[r] + b;
    }
}

// ---------------- CSR build (once per launch) ----------------
__global__ void zero_deg_kernel() {
    int i = blockIdx.x * blockDim.x + threadIdx.x;
    if (i < N_NODES) g_deg[i] = 0;
}
__global__ void count_kernel(const int* __restrict__ dst) {
    int e = blockIdx.x * blockDim.x + threadIdx.x;
    if (e < N_EDGES) atomicAdd(&g_deg[dst[e]], 1);
}
__global__ void __launch_bounds__(1024) scan_kernel() {
    const int CH = (N_NODES + 1023) / 1024;   // 98
    const int tid = threadIdx.x;
    const int base = tid * CH;
    int s = 0;
    for (int i = 0; i < CH; i++) {
        int idx = base + i;
        if (idx < N_NODES) s += g_deg[idx];
    }
    __shared__ int bs[1024];
    bs[tid] = s;
    __syncthreads();
    for (int off = 1; off < 1024; off <<= 1) {
        int v = (tid >= off) ? bs[tid - off] : 0;
        __syncthreads();
        bs[tid] += v;
        __syncthreads();
    }
    int running = bs[tid] - s;   // exclusive prefix
    for (int i = 0; i < CH; i++) {
        int idx = base + i;
        if (idx < N_NODES) {
            g_off[idx] = running;
            running += g_deg[idx];
            g_fill[idx] = 0;
        }
    }
    if (tid == 1023) g_off[N_NODES] = bs[1023];
}
__global__ void fill_kernel(const int* __restrict__ src, const int* __restrict__ dst) {
    int e = blockIdx.x * blockDim.x + threadIdx.x;
    if (e >= N_EDGES) return;
    int d = dst[e];
    int pos = g_off[d] + atomicAdd(&g_fill[d], 1);
    g_csr[pos] = src[e];
}

// ---------------- gather: z[n] = (1+eps)*h[n] + sum_{j in CSR[n]} h[j] ----------------
__global__ void __launch_bounds__(256) gather_kernel(const float* __restrict__ eps, int l) {
    const int tid = threadIdx.x;
    const int node = blockIdx.x * 4 + (tid >> 6);
    const int lane = tid & 63;
    if (node >= N_NODES) return;
    const float s = 1.f + eps[l];
    const int lo = g_off[node];
    const int hi = g_off[node + 1];
    const float4* h4 = reinterpret_cast<const float4*>(g_h);
    float4 a = h4[node * 64 + lane];
    a.x *= s; a.y *= s; a.z *= s; a.w *= s;
    for (int i = lo; i < hi; i++) {
        int sr = g_csr[i];
        float4 v = h4[sr * 64 + lane];
        a.x += v.x; a.y += v.y; a.z += v.z; a.w += v.w;
    }
    reinterpret_cast<float4*>(g_z)[node * 64 + lane] = a;
}

// ---------------- BN ----------------
__global__ void zero_stats_kernel() {
    g_colsum[threadIdx.x] = 0.f;
    g_colsq[threadIdx.x] = 0.f;
}
__global__ void bn_stats_kernel() {
    const int col = threadIdx.x;
    const int rows = (N_NODES + gridDim.x - 1) / gridDim.x;
    const int r0 = blockIdx.x * rows;
    const int r1 = min(r0 + rows, N_NODES);
    float s = 0.f, q = 0.f;
    for (int r = r0; r < r1; r++) {
        float v = g_z[r * HID + col];
        s += v;
        q = fmaf(v, v, q);
    }
    atomicAdd(&g_colsum[col], s);
    atomicAdd(&g_colsq[col], q);
}
__global__ void bn_finalize_kernel(const float* __restrict__ gammas,
                                   const float* __restrict__ betas, int l) {
    const int c = threadIdx.x;
    const float inv = 1.f / (float)N_NODES;
    float mu = g_colsum[c] * inv;
    float var = g_colsq[c] * inv - mu * mu;
    float rs = rsqrtf(var + BN_EPS);
    float sc = gammas[l * HID + c] * rs;
    g_scale[c] = sc;
    g_shift[c] = betas[l * HID + c] - mu * sc;
}
__global__ void bn_apply_kernel() {
    const int n4 = N_NODES * HID / 4;
    const float4* z4 = reinterpret_cast<const float4*>(g_z);
    float4* h4 = reinterpret_cast<float4*>(g_h);
    for (int i = blockIdx.x * blockDim.x + threadIdx.x; i < n4;
         i += gridDim.x * blockDim.x) {
        int col = (i * 4) & (HID - 1);
        float4 v = z4[i];
        float4 sc = *reinterpret_cast<const float4*>(g_scale + col);
        float4 sh = *reinterpret_cast<const float4*>(g_shift + col);
        v.x = fmaxf(fmaf(v.x, sc.x, sh.x), 0.f);
        v.y = fmaxf(fmaf(v.y, sc.y, sh.y), 0.f);
        v.z = fmaxf(fmaf(v.z, sc.z, sh.z), 0.f);
        v.w = fmaxf(fmaf(v.w, sc.w, sh.w), 0.f);
        h4[i] = v;
    }
}

// ---------------- pooling (batch is sorted): one block per graph ----------------
__global__ void pool_kernel(const int* __restrict__ batch) {
    const int g = blockIdx.x;
    const int col = threadIdx.x;
    __shared__ int s_lo, s_hi;
    if (col < 2) {
        int target = g + col;
        int lo = 0, hi = N_NODES;
        while (lo < hi) {
            int mid = (lo + hi) >> 1;
            if (batch[mid] < target) lo = mid + 1; else hi = mid;
        }
        if (col == 0) s_lo = lo; else s_hi = lo;
    }
    __syncthreads();
    const int lo = s_lo, hi = s_hi;
    float s = 0.f;
    for (int r = lo; r < hi; r++) s += g_h[r * HID + col];
    g_pool[g * HID + col] = s / fmaxf((float)(hi - lo), 1.f);
}

// ---------------- readout SGEMM (fp32 SIMT, small M) ----------------
template <bool RELU>
__global__ void __launch_bounds__(256) sgemm_kernel(const float* __restrict__ A,
                                                    const float* __restrict__ B,
                                                    const float* __restrict__ bias,
                                                    float* __restrict__ C,
                                                    int M, int N, int K) {
    __shared__ float As[8][128];
    __shared__ float Bs[8][128];
    const int tid = threadIdx.x;
    const int row0 = blockIdx.x * 128;
    const int col0 = blockIdx.y * 128;
    const int tr = (tid >> 4) << 3;
    const int tc = (tid & 15) << 3;
    const int arow = tid >> 1;
    const int ak4 = (tid & 1) * 4;
    const int brow = tid >> 5;
    const int bcol = (tid & 31) * 4;
    float acc[8][8];
#pragma unroll
    for (int i = 0; i < 8; i++)
#pragma unroll
        for (int j = 0; j < 8; j++) acc[i][j] = 0.f;
    const int gar = row0 + arow;
    const bool arow_ok = (gar < M);
    for (int k0 = 0; k0 < K; k0 += 8) {
        float4 av = make_float4(0.f, 0.f, 0.f, 0.f);
        if (arow_ok)
            av = *reinterpret_cast<const float4*>(A + (size_t)gar * K + k0 + ak4);
        As[ak4 + 0][arow] = av.x;
        As[ak4 + 1][arow] = av.y;
        As[ak4 + 2][arow] = av.z;
        As[ak4 + 3][arow] = av.w;
        float4 bv = *reinterpret_cast<const float4*>(B + (size_t)(k0 + brow) * N + col0 + bcol);
        *reinterpret_cast<float4*>(&Bs[brow][bcol]) = bv;
        __syncthreads();
#pragma unroll
        for (int k = 0; k < 8; k++) {
            float ra[8], rb[8];
#pragma unroll
            for (int i = 0; i < 8; i++) ra[i] = As[k][tr + i];
#pragma unroll
            for (int j = 0; j < 8; j++) rb[j] = Bs[k][tc + j];
#pragma unroll
            for (int i = 0; i < 8; i++)
#pragma unroll
                for (int j = 0; j < 8; j++) acc[i][j] = fmaf(ra[i], rb[j], acc[i][j]);
        }
        __syncthreads();
    }
#pragma unroll
    for (int i = 0; i < 8; i++) {
        int r = row0 + tr + i;
        if (r >= M) break;
#pragma unroll
        for (int j = 0; j < 8; j += 4) {
            float4 v;
            v.x = acc[i][j + 0] + bias[col0 + tc + j + 0];
            v.y = acc[i][j + 1] + bias[col0 + tc + j + 1];
            v.z = acc[i][j + 2] + bias[col0 + tc + j + 2];
            v.w = acc[i][j + 3] + bias[col0 + tc + j + 3];
            if (RELU) {
                v.x = fmaxf(v.x, 0.f); v.y = fmaxf(v.y, 0.f);
                v.z = fmaxf(v.z, 0.f); v.w = fmaxf(v.w, 0.f);
            }
            *reinterpret_cast<float4*>(C + (size_t)r * N + col0 + tc + j) = v;
        }
    }
}

__global__ void readout2_kernel(const float* __restrict__ Wr2,
                                const float* __restrict__ br2,
                                float* __restrict__ out) {
    __shared__ float red[256];
    const int g = blockIdx.x;
    const int t = threadIdx.x;
    red[t] = g_r1[g * HID + t] * Wr2[t];
    __syncthreads();
    for (int s = 128; s > 0; s >>= 1) {
        if (t < s) red[t] += red[t + s];
        __syncthreads();
    }
    if (t == 0) out[g] = red[0] + br2[0];
}

// ---------------- host launcher ----------------
extern "C" void kernel_launch(void* const* d_in, const int* in_sizes, int n_in,
                              void* d_out, int out_size) {
    const float* x      = (const float*)d_in[0];
    const int*   ei     = (const int*)d_in[1];
    const int*   batch  = (const int*)d_in[2];
    const float* Wp     = (const float*)d_in[3];
    const float* bp     = (const float*)d_in[4];
    const float* eps    = (const float*)d_in[5];
    const float* W1s    = (const float*)d_in[6];
    const float* b1s    = (const float*)d_in[7];
    const float* W2s    = (const float*)d_in[8];
    const float* b2s    = (const float*)d_in[9];
    const float* gammas = (const float*)d_in[10];
    const float* betas  = (const float*)d_in[11];
    const float* Wr1    = (const float*)d_in[12];
    const float* br1    = (const float*)d_in[13];
    const float* Wr2    = (const float*)d_in[14];
    const float* br2    = (const float*)d_in[15];
    float* out = (float*)d_out;

    const int* src = ei;
    const int* dst = ei + N_EDGES;

    void *p_z, *p_t, *p_pool, *p_r1;
    cudaGetSymbolAddress(&p_z, g_z);
    cudaGetSymbolAddress(&p_t, g_t);
    cudaGetSymbolAddress(&p_pool, g_pool);
    cudaGetSymbolAddress(&p_r1, g_r1);
    float* dz = (float*)p_z;
    float* dt = (float*)p_t;
    float* dpool = (float*)p_pool;
    float* dr1 = (float*)p_r1;

    cudaFuncSetAttribute(gemm_bf16_kernel<true>,
                         cudaFuncAttributeMaxDynamicSharedMemorySize, GEMM_SMEM);
    cudaFuncSetAttribute(gemm_bf16_kernel<false>,
                         cudaFuncAttributeMaxDynamicSharedMemorySize, GEMM_SMEM);

    // CSR build (edges constant across layers)
    zero_deg_kernel<<<(N_NODES + 255) / 256, 256>>>();
    count_kernel<<<(N_EDGES + 255) / 256, 256>>>(dst);
    scan_kernel<<<1, 1024>>>();
    fill_kernel<<<(N_EDGES + 255) / 256, 256>>>(src, dst);

    // projection
    proj_kernel<<<(N_NODES + 31) / 32, 256>>>(x, Wp, bp);

    const dim3 ggrid((N_NODES + 127) / 128, 2);

    for (int l = 0; l < LAYERS; l++) {
        gather_kernel<<<N_NODES / 4, 256>>>(eps, l);
        gemm_bf16_kernel<true><<<ggrid, 256, GEMM_SMEM>>>(
            dz, W1s + l * HID * HID, b1s + l * HID, dt, N_NODES);
        gemm_bf16_kernel<false><<<ggrid, 256, GEMM_SMEM>>>(
            dt, W2s + l * HID * HID, b2s + l * HID, dz, N_NODES);
        zero_stats_kernel<<<1, 256>>>();
        bn_stats_kernel<<<512, 256>>>();
        bn_finalize_kernel<<<1, 256>>>(gammas, betas, l);
        bn_apply_kernel<<<2048, 256>>>();
    }

    pool_kernel<<<N_GRAPHS, 256>>>(batch);

    const dim3 rgrid(N_GRAPHS / 128, HID / 128);
    sgemm_kernel<true><<<rgrid, 256>>>(dpool, Wr1, br1, dr1, N_GRAPHS, HID, HID);
    readout2_kernel<<<N_GRAPHS, 256>>>(Wr2, br2, out);
}

// round 4
// speedup vs baseline: 2.3074x; 1.8632x over previous
#include <cuda_runtime.h>
#include <cuda_bf16.h>
#include <cstdint>

#define N_NODES 100000
#define N_EDGES 300000
#define N_GRAPHS 2048
#define IN_DIM 38
#define HID 256
#define LAYERS 5
#define BN_EPS 1e-5f

// ---------------- device scratch ----------------
__device__ float g_h[N_NODES * HID];          // fp32 features (proj out / pool in)
__device__ float g_z[N_NODES * HID];          // GEMM2 output (pre-BN)
__device__ uint32_t g_zp[N_NODES * HID];      // packed (bf16hi,bf16lo) GEMM1 input
__device__ uint32_t g_tp[N_NODES * HID];      // packed GEMM1 output / GEMM2 input
__device__ __nv_bfloat16 g_whi[2 * LAYERS * HID * HID];  // W^T hi, [mat][n][k]
__device__ __nv_bfloat16 g_wlo[2 * LAYERS * HID * HID];  // W^T lo
__device__ float g_colsum[HID];
__device__ float g_colsq[HID];
__device__ float g_scale[HID];
__device__ float g_shift[HID];
__device__ float g_pool[N_GRAPHS * HID];
__device__ float g_r1[N_GRAPHS * HID];
__device__ int g_deg[N_NODES];
__device__ int g_fill[N_NODES];
__device__ int g_off[N_NODES + 1];
__device__ int g_csr[N_EDGES];

__device__ __forceinline__ uint32_t smem_u32(const void* p) {
    uint32_t a;
    asm("{ .reg .u64 t; cvta.to.shared.u64 t, %1; cvt.u32.u64 %0, t; }"
        : "=r"(a) : "l"(p));
    return a;
}

__device__ __forceinline__ uint32_t pack_split(float v) {
    __nv_bfloat16 h = __float2bfloat16(v);
    float res = v - __bfloat162float(h);
    __nv_bfloat16 l = __float2bfloat16(res);
    return (uint32_t)(*reinterpret_cast<uint16_t*>(&h)) |
           ((uint32_t)(*reinterpret_cast<uint16_t*>(&l)) << 16);
}

#define MMA_BF16(c, a0, a1, a2, a3, b0, b1)                                    \
    asm volatile(                                                              \
        "mma.sync.aligned.m16n8k16.row.col.f32.bf16.bf16.f32 "                 \
        "{%0,%1,%2,%3}, {%4,%5,%6,%7}, {%8,%9}, {%0,%1,%2,%3};"                \
        : "+f"((c)[0]), "+f"((c)[1]), "+f"((c)[2]), "+f"((c)[3])               \
        : "r"(a0), "r"(a1), "r"(a2), "r"(a3), "r"(b0), "r"(b1))

#define CP_ASYNC16(dst, src) \
    asm volatile("cp.async.ca.shared.global [%0], [%1], 16;" \
                 :: "r"(dst), "l"(src) : "memory")
#define CP_ASYNC16_Z(dst, src, n) \
    asm volatile("cp.async.ca.shared.global [%0], [%1], 16, %2;" \
                 :: "r"(dst), "l"(src), "r"(n) : "memory")
#define CP_COMMIT() asm volatile("cp.async.commit_group;" ::: "memory")

// smem stage: A packed 128 rows x (32 u32, stride 160B) = 20480B
//             Bhi 128 n x (32 bf16, stride 80B) = 10240B ; Blo = 10240B
#define STAGES 4
#define STG 40960
#define A_ST(s)  ((s) * STG)
#define BH_ST(s) ((s) * STG + 20480)
#define BL_ST(s) ((s) * STG + 30720)
#define GEMM_SMEM (STAGES * STG)

// ============== GEMM: C[M,256] = unpack(Ap) @ (Whi+Wlo)[n][k]^T + bias ==============
// OUTMODE 0: fp32 out; OUTMODE 1: relu + packed u32 out.
template <int OUTMODE>
__global__ void __launch_bounds__(256, 1)
gemm_mma_kernel(const uint32_t* __restrict__ Ap,
                const __nv_bfloat16* __restrict__ Whi,
                const __nv_bfloat16* __restrict__ Wlo,
                const float* __restrict__ bias,
                void* __restrict__ Cout, int M) {
    extern __shared__ char sm[];
    const uint32_t smb = smem_u32(sm);
    const int tid = threadIdx.x;
    const int lane = tid & 31;
    const int wid = tid >> 5;
    const int wm = wid & 3;
    const int wn = wid >> 2;
    const int gq = lane >> 2;
    const int tq = lane & 3;
    const int row0 = blockIdx.x * 128;
    const int col0 = blockIdx.y * 128;

    float acc[2][8][4];
#pragma unroll
    for (int i = 0; i < 2; i++)
#pragma unroll
        for (int n = 0; n < 8; n++)
#pragma unroll
            for (int q = 0; q < 4; q++) acc[i][n][q] = 0.f;

    auto load_chunk = [&](int c, int s) {
        const int k0 = c * 32;
        // A: 128 rows x 128B
#pragma unroll
        for (int i = 0; i < 4; i++) {
            int idx = tid + 256 * i;
            int r = idx >> 3, q = idx & 7;
            int gr = row0 + r;
            int n = (gr < M) ? 16 : 0;
            int grc = (gr < M) ? gr : (M - 1);
            const char* src = (const char*)(Ap + (size_t)grc * HID + k0 + q * 4);
            CP_ASYNC16_Z(smb + A_ST(s) + r * 160 + q * 16, src, n);
        }
        // B: hi & lo, 128 n-rows x 64B each
#pragma unroll
        for (int i = 0; i < 4; i++) {
            int idx = tid + 256 * i;
            int half = idx >> 9, r = (idx >> 2) & 127, q = idx & 3;
            const __nv_bfloat16* W = half ? Wlo : Whi;
            const char* src = (const char*)(W + (size_t)(col0 + r) * HID + k0 + q * 8);
            uint32_t dst = smb + (half ? BL_ST(s) : BH_ST(s)) + r * 80 + q * 16;
            CP_ASYNC16(dst, src);
        }
        CP_COMMIT();
    };

    auto compute = [&](int s) {
#pragma unroll
        for (int j = 0; j < 2; j++) {
            uint32_t ah[2][4], al[2][4];
#pragma unroll
            for (int i = 0; i < 2; i++) {
                int rb = wm * 32 + i * 16;
                const char* pA = sm + A_ST(s);
                uint2 q0 = *reinterpret_cast<const uint2*>(pA + (rb + gq) * 160 + j * 64 + tq * 8);
                uint2 q1 = *reinterpret_cast<const uint2*>(pA + (rb + 8 + gq) * 160 + j * 64 + tq * 8);
                uint2 q2 = *reinterpret_cast<const uint2*>(pA + (rb + gq) * 160 + j * 64 + tq * 8 + 32);
                uint2 q3 = *reinterpret_cast<const uint2*>(pA + (rb + 8 + gq) * 160 + j * 64 + tq * 8 + 32);
                ah[i][0] = __byte_perm(q0.x, q0.y, 0x5410);
                al[i][0] = __byte_perm(q0.x, q0.y, 0x7632);
                ah[i][1] = __byte_perm(q1.x, q1.y, 0x5410);
                al[i][1] = __byte_perm(q1.x, q1.y, 0x7632);
                ah[i][2] = __byte_perm(q2.x, q2.y, 0x5410);
                al[i][2] = __byte_perm(q2.x, q2.y, 0x7632);
                ah[i][3] = __byte_perm(q3.x, q3.y, 0x5410);
                al[i][3] = __byte_perm(q3.x, q3.y, 0x7632);
            }
#pragma unroll
            for (int n = 0; n < 8; n++) {
                int cb = wn * 64 + n * 8 + gq;
                uint32_t bh0 = *reinterpret_cast<const uint32_t*>(sm + BH_ST(s) + cb * 80 + j * 32 + tq * 4);
                uint32_t bh1 = *reinterpret_cast<const uint32_t*>(sm + BH_ST(s) + cb * 80 + j * 32 + tq * 4 + 16);
                uint32_t bl0 = *reinterpret_cast<const uint32_t*>(sm + BL_ST(s) + cb * 80 + j * 32 + tq * 4);
                uint32_t bl1 = *reinterpret_cast<const uint32_t*>(sm + BL_ST(s) + cb * 80 + j * 32 + tq * 4 + 16);
#pragma unroll
                for (int i = 0; i < 2; i++) {
                    MMA_BF16(acc[i][n], ah[i][0], ah[i][1], ah[i][2], ah[i][3], bh0, bh1);
                    MMA_BF16(acc[i][n], ah[i][0], ah[i][1], ah[i][2], ah[i][3], bl0, bl1);
                    MMA_BF16(acc[i][n], al[i][0], al[i][1], al[i][2], al[i][3], bh0, bh1);
                }
            }
        }
    };

#pragma unroll
    for (int c = 0; c < STAGES; c++) load_chunk(c, c);

#pragma unroll 1
    for (int c = 0; c < 8; c++) {
        int w = 7 - c;
        if (w > 3) w = 3;
        switch (w) {
            case 3: asm volatile("cp.async.wait_group 3;" ::: "memory"); break;
            case 2: asm volatile("cp.async.wait_group 2;" ::: "memory"); break;
            case 1: asm volatile("cp.async.wait_group 1;" ::: "memory"); break;
            default: asm volatile("cp.async.wait_group 0;" ::: "memory"); break;
        }
        __syncthreads();
        compute(c & 3);
        __syncthreads();
        if (c + STAGES < 8) load_chunk(c + STAGES, c & 3);
    }

    // epilogue
#pragma unroll
    for (int i = 0; i < 2; i++) {
        int r0 = row0 + wm * 32 + i * 16 + gq;
#pragma unroll
        for (int n = 0; n < 8; n++) {
            int col = col0 + wn * 64 + n * 8 + tq * 2;
            float b0 = bias[col], b1 = bias[col + 1];
            float v0 = acc[i][n][0] + b0, v1 = acc[i][n][1] + b1;
            float v2 = acc[i][n][2] + b0, v3 = acc[i][n][3] + b1;
            if (OUTMODE == 1) {
                v0 = fmaxf(v0, 0.f); v1 = fmaxf(v1, 0.f);
                v2 = fmaxf(v2, 0.f); v3 = fmaxf(v3, 0.f);
                uint32_t* C = (uint32_t*)Cout;
                if (r0 < M) {
                    uint2 p = make_uint2(pack_split(v0), pack_split(v1));
                    *reinterpret_cast<uint2*>(C + (size_t)r0 * HID + col) = p;
                }
                if (r0 + 8 < M) {
                    uint2 p = make_uint2(pack_split(v2), pack_split(v3));
                    *reinterpret_cast<uint2*>(C + (size_t)(r0 + 8) * HID + col) = p;
                }
            } else {
                float* C = (float*)Cout;
                if (r0 < M)
                    *reinterpret_cast<float2*>(C + (size_t)r0 * HID + col) = make_float2(v0, v1);
                if (r0 + 8 < M)
                    *reinterpret_cast<float2*>(C + (size_t)(r0 + 8) * HID + col) = make_float2(v2, v3);
            }
        }
    }
}

// ---------------- W transpose + split (once per launch) ----------------
__global__ void wsplit_kernel(const float* __restrict__ W1s,
                              const float* __restrict__ W2s) {
    __shared__ float tile[32][33];
    const int m = blockIdx.z;
    const float* W = (m & 1) ? (W2s + (size_t)(m >> 1) * HID * HID)
                             : (W1s + (size_t)(m >> 1) * HID * HID);
    const int kb = blockIdx.y * 32, nb = blockIdx.x * 32;
    const int tx = threadIdx.x, ty = threadIdx.y;
#pragma unroll
    for (int i = 0; i < 32; i += 8)
        tile[ty + i][tx] = W[(size_t)(kb + ty + i) * HID + nb + tx];
    __syncthreads();
#pragma unroll
    for (int i = 0; i < 32; i += 8) {
        int n = nb + ty + i, k = kb + tx;
        float v = tile[tx][ty + i];
        __nv_bfloat16 h = __float2bfloat16(v);
        float res = v - __bfloat162float(h);
        size_t o = (size_t)m * HID * HID + (size_t)n * HID + k;
        g_whi[o] = h;
        g_wlo[o] = __float2bfloat16(res);
    }
}

// ---------------- projection: h = x @ Wp + bp ----------------
__global__ void __launch_bounds__(256) proj_kernel(const float* __restrict__ x,
                                                   const float* __restrict__ Wp,
                                                   const float* __restrict__ bp) {
    __shared__ float xs[32][IN_DIM];
    __shared__ float ws[IN_DIM * HID];
    const int tid = threadIdx.x;
    for (int i = tid; i < IN_DIM * HID; i += 256) ws[i] = Wp[i];
    const int row0 = blockIdx.x * 32;
    for (int i = tid; i < 32 * IN_DIM; i += 256) {
        int r = i / IN_DIM, k = i % IN_DIM;
        xs[r][k] = (row0 + r < N_NODES) ? x[(row0 + r) * IN_DIM + k] : 0.f;
    }
    __syncthreads();
    float acc[32];
#pragma unroll
    for (int r = 0; r < 32; r++) acc[r] = 0.f;
    const int col = tid;
#pragma unroll
    for (int k = 0; k < IN_DIM; k++) {
        float w = ws[k * HID + col];
#pragma unroll
        for (int r = 0; r < 32; r++) acc[r] = fmaf(xs[r][k], w, acc[r]);
    }
    const float b = bp[col];
    for (int r = 0; r < 32; r++) {
        int rr = row0 + r;
        if (rr < N_NODES) g_h[rr * HID + col] = acc[r] + b;
    }
}

// ---------------- CSR build ----------------
__global__ void zero_deg_kernel() {
    int i = blockIdx.x * blockDim.x + threadIdx.x;
    if (i < N_NODES) g_deg[i] = 0;
}
__global__ void count_kernel(const int* __restrict__ dst) {
    int e = blockIdx.x * blockDim.x + threadIdx.x;
    if (e < N_EDGES) atomicAdd(&g_deg[dst[e]], 1);
}
__global__ void __launch_bounds__(1024) scan_kernel() {
    const int CH = (N_NODES + 1023) / 1024;
    const int tid = threadIdx.x;
    const int base = tid * CH;
    int s = 0;
    for (int i = 0; i < CH; i++) {
        int idx = base + i;
        if (idx < N_NODES) s += g_deg[idx];
    }
    __shared__ int bs[1024];
    bs[tid] = s;
    __syncthreads();
    for (int off = 1; off < 1024; off <<= 1) {
        int v = (tid >= off) ? bs[tid - off] : 0;
        __syncthreads();
        bs[tid] += v;
        __syncthreads();
    }
    int running = bs[tid] - s;
    for (int i = 0; i < CH; i++) {
        int idx = base + i;
        if (idx < N_NODES) {
            g_off[idx] = running;
            running += g_deg[idx];
            g_fill[idx] = 0;
        }
    }
    if (tid == 1023) g_off[N_NODES] = bs[1023];
}
__global__ void fill_kernel(const int* __restrict__ src, const int* __restrict__ dst) {
    int e = blockIdx.x * blockDim.x + threadIdx.x;
    if (e >= N_EDGES) return;
    int d = dst[e];
    int pos = g_off[d] + atomicAdd(&g_fill[d], 1);
    g_csr[pos] = src[e];
}

// ---------------- gather: zp[n] = pack((1+eps)*f(in[n]) + sum f(in[j])) ----------------
// BN=false: f = identity, in = g_h. BN=true: f = relu(v*scale+shift), in = g_z.
template <bool BN>
__global__ void __launch_bounds__(256) gather_kernel(const float* __restrict__ eps, int l) {
    const int tid = threadIdx.x;
    const int node = blockIdx.x * 4 + (tid >> 6);
    const int lane = tid & 63;
    if (node >= N_NODES) return;
    const float s = 1.f + eps[l];
    const int lo = g_off[node];
    const int hi = g_off[node + 1];
    const float4* in4 = reinterpret_cast<const float4*>(BN ? g_z : g_h);
    float4 sc, sh;
    if (BN) {
        sc = *reinterpret_cast<const float4*>(g_scale + lane * 4);
        sh = *reinterpret_cast<const float4*>(g_shift + lane * 4);
    }
    auto f = [&](float4 v) {
        if (BN) {
            v.x = fmaxf(fmaf(v.x, sc.x, sh.x), 0.f);
            v.y = fmaxf(fmaf(v.y, sc.y, sh.y), 0.f);
            v.z = fmaxf(fmaf(v.z, sc.z, sh.z), 0.f);
            v.w = fmaxf(fmaf(v.w, sc.w, sh.w), 0.f);
        }
        return v;
    };
    float4 a = f(in4[node * 64 + lane]);
    a.x *= s; a.y *= s; a.z *= s; a.w *= s;
    for (int i = lo; i < hi; i++) {
        int sr = g_csr[i];
        float4 v = f(in4[sr * 64 + lane]);
        a.x += v.x; a.y += v.y; a.z += v.z; a.w += v.w;
    }
    uint4 p;
    p.x = pack_split(a.x); p.y = pack_split(a.y);
    p.z = pack_split(a.z); p.w = pack_split(a.w);
    reinterpret_cast<uint4*>(g_zp)[node * 64 + lane] = p;
}

// ---------------- BN stats ----------------
__global__ void zero_stats_kernel() {
    g_colsum[threadIdx.x] = 0.f;
    g_colsq[threadIdx.x] = 0.f;
}
__global__ void bn_stats_kernel() {
    const int col = threadIdx.x;
    const int rows = (N_NODES + gridDim.x - 1) / gridDim.x;
    const int r0 = blockIdx.x * rows;
    const int r1 = min(r0 + rows, N_NODES);
    float s = 0.f, q = 0.f;
    for (int r = r0; r < r1; r++) {
        float v = g_z[r * HID + col];
        s += v;
        q = fmaf(v, v, q);
    }
    atomicAdd(&g_colsum[col], s);
    atomicAdd(&g_colsq[col], q);
}
__global__ void bn_finalize_kernel(const float* __restrict__ gammas,
                                   const float* __restrict__ betas, int l) {
    const int c = threadIdx.x;
    const float inv = 1.f / (float)N_NODES;
    float mu = g_colsum[c] * inv;
    float var = g_colsq[c] * inv - mu * mu;
    float rs = rsqrtf(var + BN_EPS);
    float sc = gammas[l * HID + c] * rs;
    g_scale[c] = sc;
    g_shift[c] = betas[l * HID + c] - mu * sc;
}

// ---------------- pooling with fused final BN+relu ----------------
__global__ void pool_kernel(const int* __restrict__ batch) {
    const int g = blockIdx.x;
    const int col = threadIdx.x;
    __shared__ int s_lo, s_hi;
    if (col < 2) {
        int target = g + col;
        int lo = 0, hi = N_NODES;
        while (lo < hi) {
            int mid = (lo + hi) >> 1;
            if (batch[mid] < target) lo = mid + 1; else hi = mid;
        }
        if (col == 0) s_lo = lo; else s_hi = lo;
    }
    __syncthreads();
    const int lo = s_lo, hi = s_hi;
    const float sc = g_scale[col], sh = g_shift[col];
    float s = 0.f;
    for (int r = lo; r < hi; r++)
        s += fmaxf(fmaf(g_z[r * HID + col], sc, sh), 0.f);
    g_pool[g * HID + col] = s / fmaxf((float)(hi - lo), 1.f);
}

// ---------------- readout SGEMM (fp32 SIMT, small M) ----------------
template <bool RELU>
__global__ void __launch_bounds__(256) sgemm_kernel(const float* __restrict__ A,
                                                    const float* __restrict__ B,
                                                    const float* __restrict__ bias,
                                                    float* __restrict__ C,
                                                    int M, int N, int K) {
    __shared__ float As[8][128];
    __shared__ float Bs[8][128];
    const int tid = threadIdx.x;
    const int row0 = blockIdx.x * 128;
    const int col0 = blockIdx.y * 128;
    const int tr = (tid >> 4) << 3;
    const int tc = (tid & 15) << 3;
    const int arow = tid >> 1;
    const int ak4 = (tid & 1) * 4;
    const int brow = tid >> 5;
    const int bcol = (tid & 31) * 4;
    float acc[8][8];
#pragma unroll
    for (int i = 0; i < 8; i++)
#pragma unroll
        for (int j = 0; j < 8; j++) acc[i][j] = 0.f;
    const int gar = row0 + arow;
    const bool arow_ok = (gar < M);
    for (int k0 = 0; k0 < K; k0 += 8) {
        float4 av = make_float4(0.f, 0.f, 0.f, 0.f);
        if (arow_ok)
            av = *reinterpret_cast<const float4*>(A + (size_t)gar * K + k0 + ak4);
        As[ak4 + 0][arow] = av.x;
        As[ak4 + 1][arow] = av.y;
        As[ak4 + 2][arow] = av.z;
        As[ak4 + 3][arow] = av.w;
        float4 bv = *reinterpret_cast<const float4*>(B + (size_t)(k0 + brow) * N + col0 + bcol);
        *reinterpret_cast<float4*>(&Bs[brow][bcol]) = bv;
        __syncthreads();
#pragma unroll
        for (int k = 0; k < 8; k++) {
            float ra[8], rb[8];
#pragma unroll
            for (int i = 0; i < 8; i++) ra[i] = As[k][tr + i];
#pragma unroll
            for (int j = 0; j < 8; j++) rb[j] = Bs[k][tc + j];
#pragma unroll
            for (int i = 0; i < 8; i++)
#pragma unroll
                for (int j = 0; j < 8; j++) acc[i][j] = fmaf(ra[i], rb[j], acc[i][j]);
        }
        __syncthreads();
    }
#pragma unroll
    for (int i = 0; i < 8; i++) {
        int r = row0 + tr + i;
        if (r >= M) break;
#pragma unroll
        for (int j = 0; j < 8; j += 4) {
            float4 v;
            v.x = acc[i][j + 0] + bias[col0 + tc + j + 0];
            v.y = acc[i][j + 1] + bias[col0 + tc + j + 1];
            v.z = acc[i][j + 2] + bias[col0 + tc + j + 2];
            v.w = acc[i][j + 3] + bias[col0 + tc + j + 3];
            if (RELU) {
                v.x = fmaxf(v.x, 0.f); v.y = fmaxf(v.y, 0.f);
                v.z = fmaxf(v.z, 0.f); v.w = fmaxf(v.w, 0.f);
            }
            *reinterpret_cast<float4*>(C + (size_t)r * N + col0 + tc + j) = v;
        }
    }
}

__global__ void readout2_kernel(const float* __restrict__ Wr2,
                                const float* __restrict__ br2,
                                float* __restrict__ out) {
    __shared__ float red[256];
    const int g = blockIdx.x;
    const int t = threadIdx.x;
    red[t] = g_r1[g * HID + t] * Wr2[t];
    __syncthreads();
    for (int s = 128; s > 0; s >>= 1) {
        if (t < s) red[t] += red[t + s];
        __syncthreads();
    }
    if (t == 0) out[g] = red[0] + br2[0];
}

// ---------------- host launcher ----------------
extern "C" void kernel_launch(void* const* d_in, const int* in_sizes, int n_in,
                              void* d_out, int out_size) {
    const float* x      = (const float*)d_in[0];
    const int*   ei     = (const int*)d_in[1];
    const int*   batch  = (const int*)d_in[2];
    const float* Wp     = (const float*)d_in[3];
    const float* bp     = (const float*)d_in[4];
    const float* eps    = (const float*)d_in[5];
    const float* W1s    = (const float*)d_in[6];
    const float* b1s    = (const float*)d_in[7];
    const float* W2s    = (const float*)d_in[8];
    const float* b2s    = (const float*)d_in[9];
    const float* gammas = (const float*)d_in[10];
    const float* betas  = (const float*)d_in[11];
    const float* Wr1    = (const float*)d_in[12];
    const float* br1    = (const float*)d_in[13];
    const float* Wr2    = (const float*)d_in[14];
    const float* br2    = (const float*)d_in[15];
    float* out = (float*)d_out;

    const int* src = ei;
    const int* dst = ei + N_EDGES;

    void *p_z, *p_zp, *p_tp, *p_pool, *p_r1, *p_whi, *p_wlo;
    cudaGetSymbolAddress(&p_z, g_z);
    cudaGetSymbolAddress(&p_zp, g_zp);
    cudaGetSymbolAddress(&p_tp, g_tp);
    cudaGetSymbolAddress(&p_pool, g_pool);
    cudaGetSymbolAddress(&p_r1, g_r1);
    cudaGetSymbolAddress(&p_whi, g_whi);
    cudaGetSymbolAddress(&p_wlo, g_wlo);
    float* dz = (float*)p_z;
    uint32_t* dzp = (uint32_t*)p_zp;
    uint32_t* dtp = (uint32_t*)p_tp;
    float* dpool = (float*)p_pool;
    float* dr1 = (float*)p_r1;
    __nv_bfloat16* dwhi = (__nv_bfloat16*)p_whi;
    __nv_bfloat16* dwlo = (__nv_bfloat16*)p_wlo;

    cudaFuncSetAttribute(gemm_mma_kernel<0>,
                         cudaFuncAttributeMaxDynamicSharedMemorySize, GEMM_SMEM);
    cudaFuncSetAttribute(gemm_mma_kernel<1>,
                         cudaFuncAttributeMaxDynamicSharedMemorySize, GEMM_SMEM);

    // precompute: CSR + W split
    zero_deg_kernel<<<(N_NODES + 255) / 256, 256>>>();
    count_kernel<<<(N_EDGES + 255) / 256, 256>>>(dst);
    scan_kernel<<<1, 1024>>>();
    fill_kernel<<<(N_EDGES + 255) / 256, 256>>>(src, dst);
    wsplit_kernel<<<dim3(8, 8, 2 * LAYERS), dim3(32, 8)>>>(W1s, W2s);

    proj_kernel<<<(N_NODES + 31) / 32, 256>>>(x, Wp, bp);

    const dim3 ggrid((N_NODES + 127) / 128, 2);
    const size_t WSZ = (size_t)HID * HID;

    for (int l = 0; l < LAYERS; l++) {
        if (l == 0)
            gather_kernel<false><<<(N_NODES + 3) / 4, 256>>>(eps, l);
        else
            gather_kernel<true><<<(N_NODES + 3) / 4, 256>>>(eps, l);
        gemm_mma_kernel<1><<<ggrid, 256, GEMM_SMEM>>>(
            dzp, dwhi + (2 * l) * WSZ, dwlo + (2 * l) * WSZ, b1s + l * HID, dtp, N_NODES);
        gemm_mma_kernel<0><<<ggrid, 256, GEMM_SMEM>>>(
            dtp, dwhi + (2 * l + 1) * WSZ, dwlo + (2 * l + 1) * WSZ, b2s + l * HID, dz, N_NODES);
        zero_stats_kernel<<<1, 256>>>();
        bn_stats_kernel<<<512, 256>>>();
        bn_finalize_kernel<<<1, 256>>>(gammas, betas, l);
    }

    pool_kernel<<<N_GRAPHS, 256>>>(batch);

    const dim3 rgrid(N_GRAPHS / 128, HID / 128);
    sgemm_kernel<true><<<rgrid, 256>>>(dpool, Wr1, br1, dr1, N_GRAPHS, HID, HID);
    readout2_kernel<<<N_GRAPHS, 256>>>(Wr2, br2, out);
}

// round 5
// speedup vs baseline: 2.4917x; 1.0799x over previous
#include <cuda_runtime.h>
#include <cuda_bf16.h>
#include <cstdint>

#define N_NODES 100000
#define N_EDGES 300000
#define N_GRAPHS 2048
#define IN_DIM 38
#define HID 256
#define LAYERS 5
#define BN_EPS 1e-5f

// ---------------- device scratch ----------------
__device__ float g_h[N_NODES * HID];          // fp32 features (proj out)
__device__ float g_z[N_NODES * HID];          // GEMM2 output (pre-BN)
__device__ uint32_t g_zp[N_NODES * HID];      // packed (bf16hi,bf16lo) GEMM1 input
__device__ uint32_t g_tp[N_NODES * HID];      // packed GEMM1 out / GEMM2 in
__device__ __nv_bfloat16 g_whi[2 * LAYERS * HID * HID];  // W^T hi, [mat][n][k]
__device__ __nv_bfloat16 g_wlo[2 * LAYERS * HID * HID];  // W^T lo
__device__ float g_colsum2[2][HID];
__device__ float g_colsq2[2][HID];
__device__ float g_pool[N_GRAPHS * HID];
__device__ float g_r1[N_GRAPHS * HID];
__device__ int g_deg[N_NODES];
__device__ int g_fill[N_NODES];
__device__ int g_off[N_NODES + 1];
__device__ int g_csr[N_EDGES];

__device__ __forceinline__ uint32_t smem_u32(const void* p) {
    uint32_t a;
    asm("{ .reg .u64 t; cvta.to.shared.u64 t, %1; cvt.u32.u64 %0, t; }"
        : "=r"(a) : "l"(p));
    return a;
}

__device__ __forceinline__ uint32_t pack_split(float v) {
    __nv_bfloat16 h = __float2bfloat16(v);
    float res = v - __bfloat162float(h);
    __nv_bfloat16 l = __float2bfloat16(res);
    return (uint32_t)(*reinterpret_cast<uint16_t*>(&h)) |
           ((uint32_t)(*reinterpret_cast<uint16_t*>(&l)) << 16);
}

#define MMA_BF16(c, a0, a1, a2, a3, b0, b1)                                    \
    asm volatile(                                                              \
        "mma.sync.aligned.m16n8k16.row.col.f32.bf16.bf16.f32 "                 \
        "{%0,%1,%2,%3}, {%4,%5,%6,%7}, {%8,%9}, {%0,%1,%2,%3};"                \
        : "+f"((c)[0]), "+f"((c)[1]), "+f"((c)[2]), "+f"((c)[3])               \
        : "r"(a0), "r"(a1), "r"(a2), "r"(a3), "r"(b0), "r"(b1))

#define CP_ASYNC16(dst, src) \
    asm volatile("cp.async.ca.shared.global [%0], [%1], 16;" \
                 :: "r"(dst), "l"(src) : "memory")
#define CP_ASYNC16_Z(dst, src, n) \
    asm volatile("cp.async.ca.shared.global [%0], [%1], 16, %2;" \
                 :: "r"(dst), "l"(src), "r"(n) : "memory")
#define CP_COMMIT() asm volatile("cp.async.commit_group;" ::: "memory")

// smem stage: A packed 128 rows x (32 u32, stride 160B) = 20480B
//             Bhi 128 n x (32 bf16, stride 80B) = 10240B ; Blo = 10240B
#define STG 40960
#define A_ST(s)  ((s) * STG)
#define BH_ST(s) ((s) * STG + 20480)
#define BL_ST(s) ((s) * STG + 30720)
#define GEMM_SMEM (2 * STG)

// ============== GEMM: C[M,256] = unpack(Ap) @ (Whi+Wlo)[n][k]^T + bias ==============
// OUTMODE 0: fp32 out + fused column sum/sumsq stats; OUTMODE 1: relu + packed u32 out.
template <int OUTMODE>
__global__ void __launch_bounds__(256, 2)
gemm_mma_kernel(const uint32_t* __restrict__ Ap,
                const __nv_bfloat16* __restrict__ Whi,
                const __nv_bfloat16* __restrict__ Wlo,
                const float* __restrict__ bias,
                void* __restrict__ Cout,
                float* __restrict__ colsum, float* __restrict__ colsq, int M) {
    extern __shared__ char sm[];
    const uint32_t smb = smem_u32(sm);
    const int tid = threadIdx.x;
    const int lane = tid & 31;
    const int wid = tid >> 5;
    const int wm = wid & 3;
    const int wn = wid >> 2;
    const int gq = lane >> 2;
    const int tq = lane & 3;
    const int row0 = blockIdx.x * 128;
    const int col0 = blockIdx.y * 128;

    float acc[2][8][4];
#pragma unroll
    for (int i = 0; i < 2; i++)
#pragma unroll
        for (int n = 0; n < 8; n++)
#pragma unroll
            for (int q = 0; q < 4; q++) acc[i][n][q] = 0.f;

    auto load_chunk = [&](int c, int s) {
        const int k0 = c * 32;
#pragma unroll
        for (int i = 0; i < 4; i++) {
            int idx = tid + 256 * i;
            int r = idx >> 3, q = idx & 7;
            int gr = row0 + r;
            int n = (gr < M) ? 16 : 0;
            int grc = (gr < M) ? gr : (M - 1);
            const char* src = (const char*)(Ap + (size_t)grc * HID + k0 + q * 4);
            CP_ASYNC16_Z(smb + A_ST(s) + r * 160 + q * 16, src, n);
        }
#pragma unroll
        for (int i = 0; i < 4; i++) {
            int idx = tid + 256 * i;
            int half = idx >> 9, r = (idx >> 2) & 127, q = idx & 3;
            const __nv_bfloat16* W = half ? Wlo : Whi;
            const char* src = (const char*)(W + (size_t)(col0 + r) * HID + k0 + q * 8);
            uint32_t dst = smb + (half ? BL_ST(s) : BH_ST(s)) + r * 80 + q * 16;
            CP_ASYNC16(dst, src);
        }
        CP_COMMIT();
    };

    auto compute = [&](int s) {
#pragma unroll
        for (int j = 0; j < 2; j++) {
            uint32_t ah[2][4], al[2][4];
#pragma unroll
            for (int i = 0; i < 2; i++) {
                int rb = wm * 32 + i * 16;
                const char* pA = sm + A_ST(s);
                uint2 q0 = *reinterpret_cast<const uint2*>(pA + (rb + gq) * 160 + j * 64 + tq * 8);
                uint2 q1 = *reinterpret_cast<const uint2*>(pA + (rb + 8 + gq) * 160 + j * 64 + tq * 8);
                uint2 q2 = *reinterpret_cast<const uint2*>(pA + (rb + gq) * 160 + j * 64 + tq * 8 + 32);
                uint2 q3 = *reinterpret_cast<const uint2*>(pA + (rb + 8 + gq) * 160 + j * 64 + tq * 8 + 32);
                ah[i][0] = __byte_perm(q0.x, q0.y, 0x5410);
                al[i][0] = __byte_perm(q0.x, q0.y, 0x7632);
                ah[i][1] = __byte_perm(q1.x, q1.y, 0x5410);
                al[i][1] = __byte_perm(q1.x, q1.y, 0x7632);
                ah[i][2] = __byte_perm(q2.x, q2.y, 0x5410);
                al[i][2] = __byte_perm(q2.x, q2.y, 0x7632);
                ah[i][3] = __byte_perm(q3.x, q3.y, 0x5410);
                al[i][3] = __byte_perm(q3.x, q3.y, 0x7632);
            }
#pragma unroll
            for (int n = 0; n < 8; n++) {
                int cb = wn * 64 + n * 8 + gq;
                uint32_t bh0 = *reinterpret_cast<const uint32_t*>(sm + BH_ST(s) + cb * 80 + j * 32 + tq * 4);
                uint32_t bh1 = *reinterpret_cast<const uint32_t*>(sm + BH_ST(s) + cb * 80 + j * 32 + tq * 4 + 16);
                uint32_t bl0 = *reinterpret_cast<const uint32_t*>(sm + BL_ST(s) + cb * 80 + j * 32 + tq * 4);
                uint32_t bl1 = *reinterpret_cast<const uint32_t*>(sm + BL_ST(s) + cb * 80 + j * 32 + tq * 4 + 16);
#pragma unroll
                for (int i = 0; i < 2; i++) {
                    MMA_BF16(acc[i][n], ah[i][0], ah[i][1], ah[i][2], ah[i][3], bh0, bh1);
                    MMA_BF16(acc[i][n], ah[i][0], ah[i][1], ah[i][2], ah[i][3], bl0, bl1);
                    MMA_BF16(acc[i][n], al[i][0], al[i][1], al[i][2], al[i][3], bh0, bh1);
                }
            }
        }
    };

    load_chunk(0, 0);
    load_chunk(1, 1);

#pragma unroll 1
    for (int c = 0; c < 8; c++) {
        if (c < 6) asm volatile("cp.async.wait_group 1;" ::: "memory");
        else       asm volatile("cp.async.wait_group 0;" ::: "memory");
        __syncthreads();
        compute(c & 1);
        __syncthreads();
        if (c + 2 < 8) load_chunk(c + 2, c & 1);
    }

    // ---------------- epilogue ----------------
    if (OUTMODE == 1) {
#pragma unroll
        for (int i = 0; i < 2; i++) {
            int r0 = row0 + wm * 32 + i * 16 + gq;
#pragma unroll
            for (int n = 0; n < 8; n++) {
                int col = col0 + wn * 64 + n * 8 + tq * 2;
                float b0 = bias[col], b1 = bias[col + 1];
                float v0 = fmaxf(acc[i][n][0] + b0, 0.f);
                float v1 = fmaxf(acc[i][n][1] + b1, 0.f);
                float v2 = fmaxf(acc[i][n][2] + b0, 0.f);
                float v3 = fmaxf(acc[i][n][3] + b1, 0.f);
                uint32_t* C = (uint32_t*)Cout;
                if (r0 < M) {
                    uint2 p = make_uint2(pack_split(v0), pack_split(v1));
                    *reinterpret_cast<uint2*>(C + (size_t)r0 * HID + col) = p;
                }
                if (r0 + 8 < M) {
                    uint2 p = make_uint2(pack_split(v2), pack_split(v3));
                    *reinterpret_cast<uint2*>(C + (size_t)(r0 + 8) * HID + col) = p;
                }
            }
        }
    } else {
        float s[16], q[16];
#pragma unroll
        for (int k = 0; k < 16; k++) { s[k] = 0.f; q[k] = 0.f; }
#pragma unroll
        for (int i = 0; i < 2; i++) {
            int r0 = row0 + wm * 32 + i * 16 + gq;
            bool ok0 = (r0 < M), ok1 = (r0 + 8 < M);
#pragma unroll
            for (int n = 0; n < 8; n++) {
                int col = col0 + wn * 64 + n * 8 + tq * 2;
                float b0 = bias[col], b1 = bias[col + 1];
                float v0 = acc[i][n][0] + b0, v1 = acc[i][n][1] + b1;
                float v2 = acc[i][n][2] + b0, v3 = acc[i][n][3] + b1;
                float* C = (float*)Cout;
                if (ok0)
                    *reinterpret_cast<float2*>(C + (size_t)r0 * HID + col) = make_float2(v0, v1);
                if (ok1)
                    *reinterpret_cast<float2*>(C + (size_t)(r0 + 8) * HID + col) = make_float2(v2, v3);
                float a0 = ok0 ? v0 : 0.f, a1 = ok0 ? v1 : 0.f;
                float a2 = ok1 ? v2 : 0.f, a3 = ok1 ? v3 : 0.f;
                s[n * 2 + 0] += a0 + a2;
                s[n * 2 + 1] += a1 + a3;
                q[n * 2 + 0] += a0 * a0 + a2 * a2;
                q[n * 2 + 1] += a1 * a1 + a3 * a3;
            }
        }
#pragma unroll
        for (int k = 0; k < 16; k++) {
#pragma unroll
            for (int off = 4; off < 32; off <<= 1) {
                s[k] += __shfl_xor_sync(0xffffffffu, s[k], off);
                q[k] += __shfl_xor_sync(0xffffffffu, q[k], off);
            }
        }
        if (lane < 4) {
#pragma unroll
            for (int k = 0; k < 16; k++) {
                int col = col0 + wn * 64 + (k >> 1) * 8 + lane * 2 + (k & 1);
                atomicAdd(&colsum[col], s[k]);
                atomicAdd(&colsq[col], q[k]);
            }
        }
    }
}

// ---------------- W transpose + split (once per launch) ----------------
__global__ void wsplit_kernel(const float* __restrict__ W1s,
                              const float* __restrict__ W2s) {
    __shared__ float tile[32][33];
    const int m = blockIdx.z;
    const float* W = (m & 1) ? (W2s + (size_t)(m >> 1) * HID * HID)
                             : (W1s + (size_t)(m >> 1) * HID * HID);
    const int kb = blockIdx.y * 32, nb = blockIdx.x * 32;
    const int tx = threadIdx.x, ty = threadIdx.y;
#pragma unroll
    for (int i = 0; i < 32; i += 8)
        tile[ty + i][tx] = W[(size_t)(kb + ty + i) * HID + nb + tx];
    __syncthreads();
#pragma unroll
    for (int i = 0; i < 32; i += 8) {
        int n = nb + ty + i, k = kb + tx;
        float v = tile[tx][ty + i];
        __nv_bfloat16 h = __float2bfloat16(v);
        float res = v - __bfloat162float(h);
        size_t o = (size_t)m * HID * HID + (size_t)n * HID + k;
        g_whi[o] = h;
        g_wlo[o] = __float2bfloat16(res);
    }
}

// ---------------- projection: h = x @ Wp + bp ----------------
__global__ void __launch_bounds__(256) proj_kernel(const float* __restrict__ x,
                                                   const float* __restrict__ Wp,
                                                   const float* __restrict__ bp) {
    __shared__ float xs[32][IN_DIM];
    __shared__ float ws[IN_DIM * HID];
    const int tid = threadIdx.x;
    for (int i = tid; i < IN_DIM * HID; i += 256) ws[i] = Wp[i];
    const int row0 = blockIdx.x * 32;
    for (int i = tid; i < 32 * IN_DIM; i += 256) {
        int r = i / IN_DIM, k = i % IN_DIM;
        xs[r][k] = (row0 + r < N_NODES) ? x[(row0 + r) * IN_DIM + k] : 0.f;
    }
    __syncthreads();
    float acc[32];
#pragma unroll
    for (int r = 0; r < 32; r++) acc[r] = 0.f;
    const int col = tid;
#pragma unroll
    for (int k = 0; k < IN_DIM; k++) {
        float w = ws[k * HID + col];
#pragma unroll
        for (int r = 0; r < 32; r++) acc[r] = fmaf(xs[r][k], w, acc[r]);
    }
    const float b = bp[col];
    for (int r = 0; r < 32; r++) {
        int rr = row0 + r;
        if (rr < N_NODES) g_h[rr * HID + col] = acc[r] + b;
    }
}

// ---------------- CSR build ----------------
__global__ void zero_deg_kernel() {
    int i = blockIdx.x * blockDim.x + threadIdx.x;
    if (i < N_NODES) g_deg[i] = 0;
}
__global__ void count_kernel(const int* __restrict__ dst) {
    int e = blockIdx.x * blockDim.x + threadIdx.x;
    if (e < N_EDGES) atomicAdd(&g_deg[dst[e]], 1);
}
__global__ void __launch_bounds__(1024) scan_kernel() {
    const int CH = (N_NODES + 1023) / 1024;
    const int tid = threadIdx.x;
    const int base = tid * CH;
    int s = 0;
    for (int i = 0; i < CH; i++) {
        int idx = base + i;
        if (idx < N_NODES) s += g_deg[idx];
    }
    __shared__ int bs[1024];
    bs[tid] = s;
    __syncthreads();
    for (int off = 1; off < 1024; off <<= 1) {
        int v = (tid >= off) ? bs[tid - off] : 0;
        __syncthreads();
        bs[tid] += v;
        __syncthreads();
    }
    int running = bs[tid] - s;
    for (int i = 0; i < CH; i++) {
        int idx = base + i;
        if (idx < N_NODES) {
            g_off[idx] = running;
            running += g_deg[idx];
            g_fill[idx] = 0;
        }
    }
    if (tid == 1023) g_off[N_NODES] = bs[1023];
}
__global__ void fill_kernel(const int* __restrict__ src, const int* __restrict__ dst) {
    int e = blockIdx.x * blockDim.x + threadIdx.x;
    if (e >= N_EDGES) return;
    int d = dst[e];
    int pos = g_off[d] + atomicAdd(&g_fill[d], 1);
    g_csr[pos] = src[e];
}

// ------- gather: zp[n] = pack((1+eps)*f(in[n]) + sum f(in[j])); zero next stats -------
// BN=false: f = identity, in = g_h. BN=true: f = relu(v*scale+shift), in = g_z,
// scale/shift computed inline from layer (l-1) stats + gamma/beta.
template <bool BN>
__global__ void __launch_bounds__(256) gather_kernel(const float* __restrict__ eps, int l,
                                                     const float* __restrict__ gammas,
                                                     const float* __restrict__ betas) {
    const int tid = threadIdx.x;
    // zero the stats buffer this layer's GEMM2 will accumulate into
    if (blockIdx.x == 0) {
        g_colsum2[l & 1][tid] = 0.f;
        g_colsq2[l & 1][tid] = 0.f;
    }
    const int node = blockIdx.x * 4 + (tid >> 6);
    const int lane = tid & 63;
    if (node >= N_NODES) return;
    const float s = 1.f + eps[l];
    const int lo = g_off[node];
    const int hi = g_off[node + 1];
    const float4* in4 = reinterpret_cast<const float4*>(BN ? g_z : g_h);
    float4 sc, sh;
    if (BN) {
        const int pp = (l - 1) & 1;
        const float inv = 1.f / (float)N_NODES;
        float scv[4], shv[4];
#pragma unroll
        for (int j = 0; j < 4; j++) {
            int c = lane * 4 + j;
            float mu = g_colsum2[pp][c] * inv;
            float var = g_colsq2[pp][c] * inv - mu * mu;
            float rs = rsqrtf(var + BN_EPS);
            scv[j] = gammas[(l - 1) * HID + c] * rs;
            shv[j] = betas[(l - 1) * HID + c] - mu * scv[j];
        }
        sc = make_float4(scv[0], scv[1], scv[2], scv[3]);
        sh = make_float4(shv[0], shv[1], shv[2], shv[3]);
    }
    auto f = [&](float4 v) {
        if (BN) {
            v.x = fmaxf(fmaf(v.x, sc.x, sh.x), 0.f);
            v.y = fmaxf(fmaf(v.y, sc.y, sh.y), 0.f);
            v.z = fmaxf(fmaf(v.z, sc.z, sh.z), 0.f);
            v.w = fmaxf(fmaf(v.w, sc.w, sh.w), 0.f);
        }
        return v;
    };
    float4 a = f(in4[node * 64 + lane]);
    a.x *= s; a.y *= s; a.z *= s; a.w *= s;
    for (int i = lo; i < hi; i++) {
        int sr = g_csr[i];
        float4 v = f(in4[sr * 64 + lane]);
        a.x += v.x; a.y += v.y; a.z += v.z; a.w += v.w;
    }
    uint4 p;
    p.x = pack_split(a.x); p.y = pack_split(a.y);
    p.z = pack_split(a.z); p.w = pack_split(a.w);
    reinterpret_cast<uint4*>(g_zp)[node * 64 + lane] = p;
}

// ---------------- pooling with fused final BN+relu (stats parity 0) ----------------
__global__ void pool_kernel(const int* __restrict__ batch,
                            const float* __restrict__ gammas,
                            const float* __restrict__ betas) {
    const int g = blockIdx.x;
    const int col = threadIdx.x;
    __shared__ int s_lo, s_hi;
    if (col < 2) {
        int target = g + col;
        int lo = 0, hi = N_NODES;
        while (lo < hi) {
            int mid = (lo + hi) >> 1;
            if (batch[mid] < target) lo = mid + 1; else hi = mid;
        }
        if (col == 0) s_lo = lo; else s_hi = lo;
    }
    __syncthreads();
    const int lo = s_lo, hi = s_hi;
    const float inv = 1.f / (float)N_NODES;
    const float mu = g_colsum2[0][col] * inv;
    const float var = g_colsq2[0][col] * inv - mu * mu;
    const float rs = rsqrtf(var + BN_EPS);
    const float sc = gammas[(LAYERS - 1) * HID + col] * rs;
    const float sh = betas[(LAYERS - 1) * HID + col] - mu * sc;
    float s = 0.f;
    for (int r = lo; r < hi; r++)
        s += fmaxf(fmaf(g_z[r * HID + col], sc, sh), 0.f);
    g_pool[g * HID + col] = s / fmaxf((float)(hi - lo), 1.f);
}

// ---------------- readout SGEMM (fp32 SIMT, small M) ----------------
template <bool RELU>
__global__ void __launch_bounds__(256) sgemm_kernel(const float* __restrict__ A,
                                                    const float* __restrict__ B,
                                                    const float* __restrict__ bias,
                                                    float* __restrict__ C,
                                                    int M, int N, int K) {
    __shared__ float As[8][128];
    __shared__ float Bs[8][128];
    const int tid = threadIdx.x;
    const int row0 = blockIdx.x * 128;
    const int col0 = blockIdx.y * 128;
    const int tr = (tid >> 4) << 3;
    const int tc = (tid & 15) << 3;
    const int arow = tid >> 1;
    const int ak4 = (tid & 1) * 4;
    const int brow = tid >> 5;
    const int bcol = (tid & 31) * 4;
    float acc[8][8];
#pragma unroll
    for (int i = 0; i < 8; i++)
#pragma unroll
        for (int j = 0; j < 8; j++) acc[i][j] = 0.f;
    const int gar = row0 + arow;
    const bool arow_ok = (gar < M);
    for (int k0 = 0; k0 < K; k0 += 8) {
        float4 av = make_float4(0.f, 0.f, 0.f, 0.f);
        if (arow_ok)
            av = *reinterpret_cast<const float4*>(A + (size_t)gar * K + k0 + ak4);
        As[ak4 + 0][arow] = av.x;
        As[ak4 + 1][arow] = av.y;
        As[ak4 + 2][arow] = av.z;
        As[ak4 + 3][arow] = av.w;
        float4 bv = *reinterpret_cast<const float4*>(B + (size_t)(k0 + brow) * N + col0 + bcol);
        *reinterpret_cast<float4*>(&Bs[brow][bcol]) = bv;
        __syncthreads();
#pragma unroll
        for (int k = 0; k < 8; k++) {
            float ra[8], rb[8];
#pragma unroll
            for (int i = 0; i < 8; i++) ra[i] = As[k][tr + i];
#pragma unroll
            for (int j = 0; j < 8; j++) rb[j] = Bs[k][tc + j];
#pragma unroll
            for (int i = 0; i < 8; i++)
#pragma unroll
                for (int j = 0; j < 8; j++) acc[i][j] = fmaf(ra[i], rb[j], acc[i][j]);
        }
        __syncthreads();
    }
#pragma unroll
    for (int i = 0; i < 8; i++) {
        int r = row0 + tr + i;
        if (r >= M) break;
#pragma unroll
        for (int j = 0; j < 8; j += 4) {
            float4 v;
            v.x = acc[i][j + 0] + bias[col0 + tc + j + 0];
            v.y = acc[i][j + 1] + bias[col0 + tc + j + 1];
            v.z = acc[i][j + 2] + bias[col0 + tc + j + 2];
            v.w = acc[i][j + 3] + bias[col0 + tc + j + 3];
            if (RELU) {
                v.x = fmaxf(v.x, 0.f); v.y = fmaxf(v.y, 0.f);
                v.z = fmaxf(v.z, 0.f); v.w = fmaxf(v.w, 0.f);
            }
            *reinterpret_cast<float4*>(C + (size_t)r * N + col0 + tc + j) = v;
        }
    }
}

__global__ void readout2_kernel(const float* __restrict__ Wr2,
                                const float* __restrict__ br2,
                                float* __restrict__ out) {
    __shared__ float red[256];
    const int g = blockIdx.x;
    const int t = threadIdx.x;
    red[t] = g_r1[g * HID + t] * Wr2[t];
    __syncthreads();
    for (int s = 128; s > 0; s >>= 1) {
        if (t < s) red[t] += red[t + s];
        __syncthreads();
    }
    if (t == 0) out[g] = red[0] + br2[0];
}

// ---------------- host launcher ----------------
extern "C" void kernel_launch(void* const* d_in, const int* in_sizes, int n_in,
                              void* d_out, int out_size) {
    const float* x      = (const float*)d_in[0];
    const int*   ei     = (const int*)d_in[1];
    const int*   batch  = (const int*)d_in[2];
    const float* Wp     = (const float*)d_in[3];
    const float* bp     = (const float*)d_in[4];
    const float* eps    = (const float*)d_in[5];
    const float* W1s    = (const float*)d_in[6];
    const float* b1s    = (const float*)d_in[7];
    const float* W2s    = (const float*)d_in[8];
    const float* b2s    = (const float*)d_in[9];
    const float* gammas = (const float*)d_in[10];
    const float* betas  = (const float*)d_in[11];
    const float* Wr1    = (const float*)d_in[12];
    const float* br1    = (const float*)d_in[13];
    const float* Wr2    = (const float*)d_in[14];
    const float* br2    = (const float*)d_in[15];
    float* out = (float*)d_out;

    const int* src = ei;
    const int* dst = ei + N_EDGES;

    void *p_z, *p_zp, *p_tp, *p_pool, *p_r1, *p_whi, *p_wlo, *p_cs, *p_cq;
    cudaGetSymbolAddress(&p_z, g_z);
    cudaGetSymbolAddress(&p_zp, g_zp);
    cudaGetSymbolAddress(&p_tp, g_tp);
    cudaGetSymbolAddress(&p_pool, g_pool);
    cudaGetSymbolAddress(&p_r1, g_r1);
    cudaGetSymbolAddress(&p_whi, g_whi);
    cudaGetSymbolAddress(&p_wlo, g_wlo);
    cudaGetSymbolAddress(&p_cs, g_colsum2);
    cudaGetSymbolAddress(&p_cq, g_colsq2);
    float* dz = (float*)p_z;
    uint32_t* dzp = (uint32_t*)p_zp;
    uint32_t* dtp = (uint32_t*)p_tp;
    float* dpool = (float*)p_pool;
    float* dr1 = (float*)p_r1;
    __nv_bfloat16* dwhi = (__nv_bfloat16*)p_whi;
    __nv_bfloat16* dwlo = (__nv_bfloat16*)p_wlo;
    float* dcs = (float*)p_cs;
    float* dcq = (float*)p_cq;

    cudaFuncSetAttribute(gemm_mma_kernel<0>,
                         cudaFuncAttributeMaxDynamicSharedMemorySize, GEMM_SMEM);
    cudaFuncSetAttribute(gemm_mma_kernel<1>,
                         cudaFuncAttributeMaxDynamicSharedMemorySize, GEMM_SMEM);

    // precompute: CSR + W split
    zero_deg_kernel<<<(N_NODES + 255) / 256, 256>>>();
    count_kernel<<<(N_EDGES + 255) / 256, 256>>>(dst);
    scan_kernel<<<1, 1024>>>();
    fill_kernel<<<(N_EDGES + 255) / 256, 256>>>(src, dst);
    wsplit_kernel<<<dim3(8, 8, 2 * LAYERS), dim3(32, 8)>>>(W1s, W2s);

    proj_kernel<<<(N_NODES + 31) / 32, 256>>>(x, Wp, bp);

    const dim3 ggrid((N_NODES + 127) / 128, 2);
    const size_t WSZ = (size_t)HID * HID;

    for (int l = 0; l < LAYERS; l++) {
        if (l == 0)
            gather_kernel<false><<<(N_NODES + 3) / 4, 256>>>(eps, l, gammas, betas);
        else
            gather_kernel<true><<<(N_NODES + 3) / 4, 256>>>(eps, l, gammas, betas);
        gemm_mma_kernel<1><<<ggrid, 256, GEMM_SMEM>>>(
            dzp, dwhi + (2 * l) * WSZ, dwlo + (2 * l) * WSZ, b1s + l * HID,
            dtp, nullptr, nullptr, N_NODES);
        gemm_mma_kernel<0><<<ggrid, 256, GEMM_SMEM>>>(
            dtp, dwhi + (2 * l + 1) * WSZ, dwlo + (2 * l + 1) * WSZ, b2s + l * HID,
            dz, dcs + (l & 1) * HID, dcq + (l & 1) * HID, N_NODES);
    }

    pool_kernel<<<N_GRAPHS, 256>>>(batch, gammas, betas);

    const dim3 rgrid(N_GRAPHS / 128, HID / 128);
    sgemm_kernel<true><<<rgrid, 256>>>(dpool, Wr1, br1, dr1, N_GRAPHS, HID, HID);
    readout2_kernel<<<N_GRAPHS, 256>>>(Wr2, br2, out);
}